// round 2
// baseline (speedup 1.0000x reference)
#include <cuda_runtime.h>
#include <math.h>

#define NPTS    (1 << 20)
#define RESG    160
#define TILE    64
#define NTILES  (NPTS / TILE)
#define SIN_RF  64     // rf row stride (broadcast reads -> no pad needed)
#define SIN_H   68     // hidden row stride (conflict-free STS.128)
#define WS1     12     // dW1t row stride
#define WSR     44     // rW1t row stride (41 padded, zeros)
#define WS2     132    // big transposed weight stride (conflict-free float4 stream)

typedef unsigned long long ull;

__device__ __forceinline__ ull fma2(ull a, ull b, ull c) {
    ull d;
    asm("fma.rn.f32x2 %0, %1, %2, %3;" : "=l"(d) : "l"(a), "l"(b), "l"(c));
    return d;
}
__device__ __forceinline__ ull dup2(float w) {
    ull d;
    asm("mov.b64 %0, {%1, %1};" : "=l"(d) : "f"(w), "f"(w));
    return d;
}

// Computes 2 output rows (j0,j1) x 16 points. in must already include +p0.
template <int K, int SIN, int WS>
__device__ __forceinline__ void layer2x16(const float* __restrict__ in,
                                          const float* __restrict__ Wt,
                                          int j0, int j1,
                                          const float* __restrict__ bias,
                                          float* __restrict__ v) {
    ull a0[8], a1[8];
#pragma unroll
    for (int m = 0; m < 8; m++) { a0[m] = 0ull; a1[m] = 0ull; }
    const float* w0p = Wt + j0 * WS;
    const float* w1p = Wt + j1 * WS;
#pragma unroll 4
    for (int k = 0; k < K; k += 4) {
        float4 w0 = *(const float4*)(w0p + k);
        float4 w1 = *(const float4*)(w1p + k);
        float wa[4] = {w0.x, w0.y, w0.z, w0.w};
        float wb[4] = {w1.x, w1.y, w1.z, w1.w};
#pragma unroll
        for (int kk = 0; kk < 4; kk++) {
            const ulonglong2* rp = (const ulonglong2*)(in + (k + kk) * SIN);
            ulonglong2 uA = rp[0], uB = rp[1];
            ull wd0 = dup2(wa[kk]), wd1 = dup2(wb[kk]);
            a0[0] = fma2(uA.x, wd0, a0[0]);
            a0[1] = fma2(uA.y, wd0, a0[1]);
            a0[2] = fma2(uB.x, wd0, a0[2]);
            a0[3] = fma2(uB.y, wd0, a0[3]);
            a1[0] = fma2(uA.x, wd1, a1[0]);
            a1[1] = fma2(uA.y, wd1, a1[1]);
            a1[2] = fma2(uB.x, wd1, a1[2]);
            a1[3] = fma2(uB.y, wd1, a1[3]);
            ulonglong2 uC = rp[2], uD = rp[3];
            a0[4] = fma2(uC.x, wd0, a0[4]);
            a0[5] = fma2(uC.y, wd0, a0[5]);
            a0[6] = fma2(uD.x, wd0, a0[6]);
            a0[7] = fma2(uD.y, wd0, a0[7]);
            a1[4] = fma2(uC.x, wd1, a1[4]);
            a1[5] = fma2(uC.y, wd1, a1[5]);
            a1[6] = fma2(uD.x, wd1, a1[6]);
            a1[7] = fma2(uD.y, wd1, a1[7]);
        }
    }
    float b0 = bias[j0], b1 = bias[j1];
#pragma unroll
    for (int m = 0; m < 8; m++) {
        ull t0 = a0[m], t1 = a1[m];
        float2 f0 = *reinterpret_cast<float2*>(&t0);
        float2 f1 = *reinterpret_cast<float2*>(&t1);
        v[2 * m]          = fmaxf(f0.x + b0, 0.f);
        v[2 * m + 1]      = fmaxf(f0.y + b0, 0.f);
        v[16 + 2 * m]     = fmaxf(f1.x + b1, 0.f);
        v[16 + 2 * m + 1] = fmaxf(f1.y + b1, 0.f);
    }
}

// Shared memory layout (floats), all offsets multiple of 4:
//  dW1t 1536 | dW2t 16896 | rW1t 5632 | rW2t 16896
//  db1 128 | db2 128 | rb1 128 | rb2 128 | dW3 128 | rW3 384 | db3 4 | rb3 4
//  rf 44*64=2816 | h1 128*68=8704 | redS 128 | redC 384
#define SMEM_FLOATS (1536 + 16896 + 5632 + 16896 + 128*4 + 128 + 384 + 8 + 2816 + 8704 + 128 + 384)
#define SMEM_BYTES  (SMEM_FLOATS * 4)

__global__ void __launch_bounds__(256, 1) fastsurf_kernel(
    const float* __restrict__ x, const float* __restrict__ grid,
    const float* __restrict__ dW1, const float* __restrict__ db1,
    const float* __restrict__ dW2, const float* __restrict__ db2,
    const float* __restrict__ dW3, const float* __restrict__ db3,
    const float* __restrict__ rW1, const float* __restrict__ rb1,
    const float* __restrict__ rW2, const float* __restrict__ rb2,
    const float* __restrict__ rW3, const float* __restrict__ rb3,
    float* __restrict__ out) {
    extern __shared__ float sm[];
    float* s_dW1t = sm;                       // 1536
    float* s_dW2t = s_dW1t + 128 * WS1;       // 16896
    float* s_rW1t = s_dW2t + 128 * WS2;       // 5632
    float* s_rW2t = s_rW1t + 128 * WSR;       // 16896
    float* s_db1  = s_rW2t + 128 * WS2;       // 128
    float* s_db2  = s_db1 + 128;
    float* s_rb1  = s_db2 + 128;
    float* s_rb2  = s_rb1 + 128;
    float* s_dW3  = s_rb2 + 128;              // 128
    float* s_rW3  = s_dW3 + 128;              // 384
    float* s_db3  = s_rW3 + 384;              // 4
    float* s_rb3  = s_db3 + 4;                // 4
    float* s_rf   = s_rb3 + 4;                // 44*64
    float* s_h1   = s_rf + 44 * SIN_RF;       // 128*68
    float* s_redS = s_h1 + 128 * SIN_H;       // 2*64
    float* s_redC = s_redS + 128;             // 3*2*64

    const int tid = threadIdx.x;

    // ---- one-time staging ----
    for (int i = tid; i < 128 * WS1; i += 256) {
        int j = i / WS1, k = i % WS1;
        s_dW1t[i] = dW1[k * 128 + j];
    }
    for (int i = tid; i < 128 * WSR; i += 256) {
        int j = i / WSR, k = i % WSR;
        s_rW1t[i] = (k < 41) ? rW1[k * 128 + j] : 0.f;
    }
    for (int i = tid; i < 16384; i += 256) {
        int k = i >> 7, j = i & 127;
        s_dW2t[j * WS2 + k] = dW2[i];
        s_rW2t[j * WS2 + k] = rW2[i];
    }
    if (tid < 128) {
        s_db1[tid] = db1[tid];
        s_db2[tid] = db2[tid];
        s_rb1[tid] = rb1[tid];
        s_rb2[tid] = rb2[tid];
        s_dW3[tid] = dW3[tid];
    }
    for (int i = tid; i < 384; i += 256) s_rW3[i] = rW3[i];
    if (tid == 0) s_db3[0] = db3[0];
    if (tid < 3) s_rb3[tid] = rb3[tid];
    // zero pad rows 41..43 of rf (never written again)
    for (int i = tid; i < 3 * SIN_RF; i += 256) s_rf[41 * SIN_RF + i] = 0.f;
    __syncthreads();

    const int lane = tid & 31;
    const int warp = tid >> 5;
    const int pg   = warp & 3;        // 4 point-groups of 16
    const int jgHi = warp >> 2;       // 0/1
    const int j0   = jgHi * 32 + lane;
    const int j1   = j0 + 64;
    const int p0   = pg * 16;

    float v[32];

    for (int tile = blockIdx.x; tile < NTILES; tile += gridDim.x) {
        const int base = tile * TILE;

        // ---- gather + featurize (8 threads/point, 2 passes of 32 points) ----
#pragma unroll
        for (int it = 0; it < 2; it++) {
            const int pp = (tid >> 3) + it * 32;
            const int corner = tid & 7;
            const float* xp = x + (size_t)(base + pp) * 8;
            float px = fminf(fmaxf(xp[0], 0.f), 1.f);
            float py = fminf(fmaxf(xp[1], 0.f), 1.f);
            float pz = fminf(fmaxf(xp[2], 0.f), 1.f);
            float fx = px * 159.f, fy = py * 159.f, fz = pz * 159.f;
            float x0 = fminf(floorf(fx), 158.f);
            float y0 = fminf(floorf(fy), 158.f);
            float z0 = fminf(floorf(fz), 158.f);
            float wx = fx - x0, wy = fy - y0, wz = fz - z0;
            int xi = (int)x0 + ((corner >> 2) & 1);
            int yi = (int)y0 + ((corner >> 1) & 1);
            int zi = (int)z0 + (corner & 1);
            float wgt = ((corner & 4) ? wx : 1.f - wx) *
                        ((corner & 2) ? wy : 1.f - wy) *
                        ((corner & 1) ? wz : 1.f - wz);
            const float* gp = grid + (size_t)((xi * RESG + yi) * RESG + zi) * 12;
            float4 g0 = *(const float4*)gp;
            float4 g1 = *(const float4*)(gp + 4);
            float4 g2 = *(const float4*)(gp + 8);
            float gv[12] = {g0.x, g0.y, g0.z, g0.w, g1.x, g1.y, g1.z, g1.w,
                            g2.x, g2.y, g2.z, g2.w};
#pragma unroll
            for (int c = 0; c < 12; c++) gv[c] *= wgt;
#pragma unroll
            for (int off = 4; off; off >>= 1)
#pragma unroll
                for (int c = 0; c < 12; c++)
                    gv[c] += __shfl_down_sync(0xffffffffu, gv[c], off);
            if (corner == 0) {
#pragma unroll
                for (int c = 0; c < 12; c++) s_rf[c * SIN_RF + pp] = gv[c];
            } else if (corner <= 3) {
                int d = corner - 1;
                float vv = xp[5 + d];
                s_rf[(12 + d) * SIN_RF + pp] = vv;
                float f = 1.f;
#pragma unroll
                for (int k = 0; k < 4; k++) {
                    s_rf[(15 + 6 * k + d) * SIN_RF + pp]     = sinf(vv * f);
                    s_rf[(15 + 6 * k + 3 + d) * SIN_RF + pp] = cosf(vv * f);
                    f *= 2.f;
                }
            } else if (corner == 4) {
                s_rf[39 * SIN_RF + pp] = xp[3];
                s_rf[40 * SIN_RF + pp] = xp[4];
            }
        }
        __syncthreads();

        // ---- density L1: 12 -> 128 ----
        layer2x16<12, SIN_RF, WS1>(s_rf + p0, s_dW1t, j0, j1, s_db1, v);
#pragma unroll
        for (int m = 0; m < 4; m++) {
            *(float4*)(s_h1 + j0 * SIN_H + p0 + 4 * m) =
                make_float4(v[4 * m], v[4 * m + 1], v[4 * m + 2], v[4 * m + 3]);
            *(float4*)(s_h1 + j1 * SIN_H + p0 + 4 * m) =
                make_float4(v[16 + 4 * m], v[17 + 4 * m], v[18 + 4 * m], v[19 + 4 * m]);
        }
        __syncthreads();

        // ---- density L2: 128 -> 128, fused sdf head ----
        layer2x16<128, SIN_H, WS2>(s_h1 + p0, s_dW2t, j0, j1, s_db2, v);
        {
            float w3a = s_dW3[j0], w3b = s_dW3[j1];
            float part[16];
#pragma unroll
            for (int p = 0; p < 16; p++)
                part[p] = fmaf(w3a, v[p], w3b * v[16 + p]);
#pragma unroll
            for (int off = 16; off; off >>= 1)
#pragma unroll
                for (int p = 0; p < 16; p++)
                    part[p] += __shfl_xor_sync(0xffffffffu, part[p], off);
            if (lane == 0) {
#pragma unroll
                for (int m = 0; m < 4; m++)
                    *(float4*)(s_redS + jgHi * 64 + p0 + 4 * m) =
                        make_float4(part[4 * m], part[4 * m + 1],
                                    part[4 * m + 2], part[4 * m + 3]);
            }
        }
        __syncthreads();

        // ---- rgb L1: 44 -> 128 (reads rf) ----
        layer2x16<WSR, SIN_RF, WSR>(s_rf + p0, s_rW1t, j0, j1, s_rb1, v);
#pragma unroll
        for (int m = 0; m < 4; m++) {
            *(float4*)(s_h1 + j0 * SIN_H + p0 + 4 * m) =
                make_float4(v[4 * m], v[4 * m + 1], v[4 * m + 2], v[4 * m + 3]);
            *(float4*)(s_h1 + j1 * SIN_H + p0 + 4 * m) =
                make_float4(v[16 + 4 * m], v[17 + 4 * m], v[18 + 4 * m], v[19 + 4 * m]);
        }
        __syncthreads();

        // ---- rgb L2: 128 -> 128, fused rgb head (3 channels) ----
        layer2x16<128, SIN_H, WS2>(s_h1 + p0, s_rW2t, j0, j1, s_rb2, v);
        {
            float pc[3][16];
#pragma unroll
            for (int c = 0; c < 3; c++) {
                float wa = s_rW3[j0 * 3 + c], wb = s_rW3[j1 * 3 + c];
#pragma unroll
                for (int p = 0; p < 16; p++)
                    pc[c][p] = fmaf(wa, v[p], wb * v[16 + p]);
            }
#pragma unroll
            for (int off = 16; off; off >>= 1)
#pragma unroll
                for (int c = 0; c < 3; c++)
#pragma unroll
                    for (int p = 0; p < 16; p++)
                        pc[c][p] += __shfl_xor_sync(0xffffffffu, pc[c][p], off);
            if (lane == 0) {
#pragma unroll
                for (int c = 0; c < 3; c++)
#pragma unroll
                    for (int m = 0; m < 4; m++)
                        *(float4*)(s_redC + c * 128 + jgHi * 64 + p0 + 4 * m) =
                            make_float4(pc[c][4 * m], pc[c][4 * m + 1],
                                        pc[c][4 * m + 2], pc[c][4 * m + 3]);
            }
        }
        __syncthreads();

        // ---- final combine + store ----
        if (tid < 64) {
            out[(size_t)(base + tid) * 4 + 3] =
                s_redS[tid] + s_redS[64 + tid] + s_db3[0];
        } else {
            int idx = tid - 64;
            int c = idx >> 6, p = idx & 63;
            out[(size_t)(base + p) * 4 + c] =
                s_redC[c * 128 + p] + s_redC[c * 128 + 64 + p] + s_rb3[c];
        }
        // no barrier needed: next-tile hazards are covered by its own barriers
    }
}

extern "C" void kernel_launch(void* const* d_in, const int* in_sizes, int n_in,
                              void* d_out, int out_size) {
    (void)in_sizes; (void)n_in; (void)out_size;
    const float* x    = (const float*)d_in[0];
    const float* grid = (const float*)d_in[1];
    const float* dW1  = (const float*)d_in[2];
    const float* db1  = (const float*)d_in[3];
    const float* dW2  = (const float*)d_in[4];
    const float* db2  = (const float*)d_in[5];
    const float* dW3  = (const float*)d_in[6];
    const float* db3  = (const float*)d_in[7];
    const float* rW1  = (const float*)d_in[8];
    const float* rb1  = (const float*)d_in[9];
    const float* rW2  = (const float*)d_in[10];
    const float* rb2  = (const float*)d_in[11];
    const float* rW3  = (const float*)d_in[12];
    const float* rb3  = (const float*)d_in[13];
    float* out = (float*)d_out;

    int nsm = 152;
    cudaDeviceGetAttribute(&nsm, cudaDevAttrMultiProcessorCount, 0);
    cudaFuncSetAttribute(fastsurf_kernel,
                         cudaFuncAttributeMaxDynamicSharedMemorySize, SMEM_BYTES);
    fastsurf_kernel<<<nsm, 256, SMEM_BYTES>>>(x, grid, dW1, db1, dW2, db2, dW3, db3,
                                              rW1, rb1, rW2, rb2, rW3, rb3, out);
}

// round 7
// speedup vs baseline: 3.6141x; 3.6141x over previous
#include <cuda_runtime.h>
#include <math.h>
#include <stdint.h>

#define NPTS   (1 << 20)
#define RESG   160
#define TILE   64
#define NTILES (NPTS / TILE)

#define WS1 20    // dW1t row stride (K=16 used, 12 real)
#define WSR 52    // rW1t row stride (K=48 used, 41 real)
#define WS2 132   // dW2t/rW2t row stride (K=128)
#define AS_RF 52  // rf stride
#define AS_H  132 // h stride

// ---- smem float offsets ----
#define F_DW1T 0
#define F_RW1T (F_DW1T + 128 * WS1)        // 2560
#define F_DW2T (F_RW1T + 128 * WSR)        // 9216
#define F_RW2T (F_DW2T + 128 * WS2)        // 26112
#define F_DB1  (F_RW2T + 128 * WS2)        // 43008
#define F_DB2  (F_DB1 + 128)
#define F_RB1  (F_DB2 + 128)
#define F_RB2  (F_RB1 + 128)
#define F_DW3  (F_RB2 + 128)
#define F_RW3  (F_DW3 + 128)               // [3][128]
#define F_DB3  (F_RW3 + 384)
#define F_RB3  (F_DB3 + 1)                 // 3
#define F_SDFP (F_RB3 + 3)                 // [2][64]
#define F_RGBP (F_SDFP + 128)              // [3][2][64]
#define F_RF   (F_RGBP + 384)              // [64][52]
#define F_H    (F_RF + 64 * AS_RF)         // [64][132]
#define SMEM_FLOATS (F_H + 64 * AS_H)
#define SMEM_BYTES  (SMEM_FLOATS * 4)

__device__ __forceinline__ float rtf32(float f) {
    uint32_t u;
    asm("cvt.rna.tf32.f32 %0, %1;" : "=r"(u) : "f"(f));
    return __uint_as_float(u);
}

__device__ __forceinline__ void mma8(float c[4], const uint32_t a[4],
                                     uint32_t b0, uint32_t b1) {
    asm volatile(
        "mma.sync.aligned.m16n8k8.row.col.f32.tf32.tf32.f32 "
        "{%0,%1,%2,%3}, {%4,%5,%6,%7}, {%8,%9}, {%0,%1,%2,%3};"
        : "+f"(c[0]), "+f"(c[1]), "+f"(c[2]), "+f"(c[3])
        : "r"(a[0]), "r"(a[1]), "r"(a[2]), "r"(a[3]), "r"(b0), "r"(b1));
}

// A: acts pre-offset to m-base row (stride AS). W: weights pre-offset to n0*WS.
// Computes m16 x n64 into c[8][4].
template <int KSTEPS, int AS, int WS>
__device__ __forceinline__ void gemm_tile(const float* __restrict__ A,
                                          const float* __restrict__ W,
                                          int lane, float c[8][4]) {
#pragma unroll
    for (int f = 0; f < 8; f++)
        c[f][0] = c[f][1] = c[f][2] = c[f][3] = 0.f;
    const int r = lane >> 2, q = lane & 3;
    const float* a0p = A + r * AS + q;
    const float* wbp = W + r * WS + q;
#pragma unroll
    for (int ks = 0; ks < KSTEPS; ks++) {
        const int k = ks * 8;
        uint32_t a[4];
        a[0] = __float_as_uint(a0p[k]);
        a[1] = __float_as_uint(a0p[8 * AS + k]);
        a[2] = __float_as_uint(a0p[k + 4]);
        a[3] = __float_as_uint(a0p[8 * AS + k + 4]);
        const float* wp = wbp + k;
#pragma unroll
        for (int f = 0; f < 8; f++) {
            uint32_t b0 = __float_as_uint(wp[f * 8 * WS]);
            uint32_t b1 = __float_as_uint(wp[f * 8 * WS + 4]);
            mma8(c[f], a, b0, b1);
        }
    }
}

__global__ void __launch_bounds__(256, 1) fastsurf_mma(
    const float* __restrict__ x, const float* __restrict__ grid,
    const float* __restrict__ dW1, const float* __restrict__ db1,
    const float* __restrict__ dW2, const float* __restrict__ db2,
    const float* __restrict__ dW3, const float* __restrict__ db3,
    const float* __restrict__ rW1, const float* __restrict__ rb1,
    const float* __restrict__ rW2, const float* __restrict__ rb2,
    const float* __restrict__ rW3, const float* __restrict__ rb3,
    float* __restrict__ out) {
    extern __shared__ float sm[];
    const int tid = threadIdx.x;

    // ---- one-time weight staging (tf32-rounded, transposed [N][K], zero pad) ----
    for (int i = tid; i < 128 * WS1; i += 256) {
        int n = i / WS1, k = i % WS1;
        sm[F_DW1T + i] = (k < 12) ? rtf32(dW1[k * 128 + n]) : 0.f;
    }
    for (int i = tid; i < 128 * WSR; i += 256) {
        int n = i / WSR, k = i % WSR;
        sm[F_RW1T + i] = (k < 41) ? rtf32(rW1[k * 128 + n]) : 0.f;
    }
    for (int i = tid; i < 128 * WS2; i += 256) {
        int n = i / WS2, k = i % WS2;
        sm[F_DW2T + i] = (k < 128) ? rtf32(dW2[k * 128 + n]) : 0.f;
        sm[F_RW2T + i] = (k < 128) ? rtf32(rW2[k * 128 + n]) : 0.f;
    }
    if (tid < 128) {
        sm[F_DB1 + tid] = db1[tid];
        sm[F_DB2 + tid] = db2[tid];
        sm[F_RB1 + tid] = rb1[tid];
        sm[F_RB2 + tid] = rb2[tid];
        sm[F_DW3 + tid] = dW3[tid];
        sm[F_RW3 + 0 * 128 + tid] = rW3[tid * 3 + 0];
        sm[F_RW3 + 1 * 128 + tid] = rW3[tid * 3 + 1];
        sm[F_RW3 + 2 * 128 + tid] = rW3[tid * 3 + 2];
    }
    if (tid == 0) sm[F_DB3] = db3[0];
    if (tid < 3) sm[F_RB3 + tid] = rb3[tid];
    // zero rf pad cols 41..51 once (must be finite; weights there are zero)
    for (int i = tid; i < 64 * 11; i += 256) {
        int row = i / 11, c = 41 + i % 11;
        sm[F_RF + row * AS_RF + c] = 0.f;
    }
    __syncthreads();

    const int lane = tid & 31, warp = tid >> 5;
    const int mi = warp & 3;          // m16 block: rows 16*mi..
    const int nh = warp >> 2;         // n64 half
    const int m0 = mi * 16;
    const int n0 = nh * 64;
    const int rr = lane >> 2, qq = lane & 3;

    const float* Wd1 = sm + F_DW1T + n0 * WS1;
    const float* Wr1 = sm + F_RW1T + n0 * WSR;
    const float* Wd2 = sm + F_DW2T + n0 * WS2;
    const float* Wr2 = sm + F_RW2T + n0 * WS2;
    float* rf = sm + F_RF;
    float* h  = sm + F_H;
    float c[8][4];

    for (int tile = blockIdx.x; tile < NTILES; tile += gridDim.x) {
        const int base = tile * TILE;

        // ---- featurize: 4 threads/point, 2 corners each ----
        {
            const int p = tid >> 2, s2 = tid & 3;
            const float* xp = x + (size_t)(base + p) * 8;
            float px = fminf(fmaxf(xp[0], 0.f), 1.f);
            float py = fminf(fmaxf(xp[1], 0.f), 1.f);
            float pz = fminf(fmaxf(xp[2], 0.f), 1.f);
            float fx = px * 159.f, fy = py * 159.f, fz = pz * 159.f;
            float x0f = fminf(floorf(fx), 158.f);
            float y0f = fminf(floorf(fy), 158.f);
            float z0f = fminf(floorf(fz), 158.f);
            float wx = fx - x0f, wy = fy - y0f, wz = fz - z0f;
            int hy = s2 >> 1, hz = s2 & 1;
            int yi = (int)y0f + hy, zi = (int)z0f + hz;
            float wyz = (hy ? wy : 1.f - wy) * (hz ? wz : 1.f - wz);
            float gv[12];
#pragma unroll
            for (int cc = 0; cc < 12; cc++) gv[cc] = 0.f;
#pragma unroll
            for (int hx = 0; hx < 2; hx++) {
                int xi = (int)x0f + hx;
                float w = (hx ? wx : 1.f - wx) * wyz;
                const float* gp = grid + (size_t)((xi * RESG + yi) * RESG + zi) * 12;
                float4 g0 = *(const float4*)gp;
                float4 g1 = *(const float4*)(gp + 4);
                float4 g2 = *(const float4*)(gp + 8);
                gv[0] = fmaf(w, g0.x, gv[0]);  gv[1] = fmaf(w, g0.y, gv[1]);
                gv[2] = fmaf(w, g0.z, gv[2]);  gv[3] = fmaf(w, g0.w, gv[3]);
                gv[4] = fmaf(w, g1.x, gv[4]);  gv[5] = fmaf(w, g1.y, gv[5]);
                gv[6] = fmaf(w, g1.z, gv[6]);  gv[7] = fmaf(w, g1.w, gv[7]);
                gv[8] = fmaf(w, g2.x, gv[8]);  gv[9] = fmaf(w, g2.y, gv[9]);
                gv[10] = fmaf(w, g2.z, gv[10]); gv[11] = fmaf(w, g2.w, gv[11]);
            }
#pragma unroll
            for (int cc = 0; cc < 12; cc++) {
                gv[cc] += __shfl_xor_sync(0xffffffffu, gv[cc], 1);
                gv[cc] += __shfl_xor_sync(0xffffffffu, gv[cc], 2);
            }
            float* rp = rf + p * AS_RF;
            if (s2 == 0) {
#pragma unroll
                for (int cc = 0; cc < 12; cc++) rp[cc] = rtf32(gv[cc]);
                rp[39] = rtf32(xp[3]);
                rp[40] = rtf32(xp[4]);
            } else {
                int d = s2 - 1;
                float vv = xp[5 + d];
                rp[12 + d] = rtf32(vv);
                float f = 1.f;
#pragma unroll
                for (int k = 0; k < 4; k++) {
                    rp[15 + 6 * k + d]     = rtf32(sinf(vv * f));
                    rp[15 + 6 * k + 3 + d] = rtf32(cosf(vv * f));
                    f *= 2.f;
                }
            }
        }
        __syncthreads();

        // ---- density L1: rf(K16) x dW1 -> h ----
        gemm_tile<2, AS_RF, WS1>(rf + m0 * AS_RF, Wd1, lane, c);
#pragma unroll
        for (int f = 0; f < 8; f++) {
            int cb = n0 + f * 8 + 2 * qq;
            float2 b = *(const float2*)(sm + F_DB1 + cb);
            float* hp = h + (m0 + rr) * AS_H + cb;
            *(float2*)hp = make_float2(rtf32(fmaxf(c[f][0] + b.x, 0.f)),
                                       rtf32(fmaxf(c[f][1] + b.y, 0.f)));
            *(float2*)(hp + 8 * AS_H) = make_float2(rtf32(fmaxf(c[f][2] + b.x, 0.f)),
                                                    rtf32(fmaxf(c[f][3] + b.y, 0.f)));
        }
        __syncthreads();

        // ---- density L2: h(K128) x dW2, fused sdf head ----
        gemm_tile<16, AS_H, WS2>(h + m0 * AS_H, Wd2, lane, c);
        {
            float psA = 0.f, psB = 0.f;
#pragma unroll
            for (int f = 0; f < 8; f++) {
                int cb = n0 + f * 8 + 2 * qq;
                float2 b  = *(const float2*)(sm + F_DB2 + cb);
                float2 w3 = *(const float2*)(sm + F_DW3 + cb);
                psA = fmaf(fmaxf(c[f][0] + b.x, 0.f), w3.x,
                      fmaf(fmaxf(c[f][1] + b.y, 0.f), w3.y, psA));
                psB = fmaf(fmaxf(c[f][2] + b.x, 0.f), w3.x,
                      fmaf(fmaxf(c[f][3] + b.y, 0.f), w3.y, psB));
            }
            psA += __shfl_xor_sync(0xffffffffu, psA, 1);
            psA += __shfl_xor_sync(0xffffffffu, psA, 2);
            psB += __shfl_xor_sync(0xffffffffu, psB, 1);
            psB += __shfl_xor_sync(0xffffffffu, psB, 2);
            if (qq == 0) {
                sm[F_SDFP + nh * 64 + m0 + rr]     = psA;
                sm[F_SDFP + nh * 64 + m0 + rr + 8] = psB;
            }
        }
        __syncthreads();

        // ---- rgb L1: rf(K48) x rW1 -> h ----
        gemm_tile<6, AS_RF, WSR>(rf + m0 * AS_RF, Wr1, lane, c);
#pragma unroll
        for (int f = 0; f < 8; f++) {
            int cb = n0 + f * 8 + 2 * qq;
            float2 b = *(const float2*)(sm + F_RB1 + cb);
            float* hp = h + (m0 + rr) * AS_H + cb;
            *(float2*)hp = make_float2(rtf32(fmaxf(c[f][0] + b.x, 0.f)),
                                       rtf32(fmaxf(c[f][1] + b.y, 0.f)));
            *(float2*)(hp + 8 * AS_H) = make_float2(rtf32(fmaxf(c[f][2] + b.x, 0.f)),
                                                    rtf32(fmaxf(c[f][3] + b.y, 0.f)));
        }
        __syncthreads();

        // ---- rgb L2: h(K128) x rW2, fused rgb head ----
        gemm_tile<16, AS_H, WS2>(h + m0 * AS_H, Wr2, lane, c);
        {
            float pA[3] = {0.f, 0.f, 0.f}, pB[3] = {0.f, 0.f, 0.f};
#pragma unroll
            for (int f = 0; f < 8; f++) {
                int cb = n0 + f * 8 + 2 * qq;
                float2 b = *(const float2*)(sm + F_RB2 + cb);
                float h0 = fmaxf(c[f][0] + b.x, 0.f);
                float h1 = fmaxf(c[f][1] + b.y, 0.f);
                float h2 = fmaxf(c[f][2] + b.x, 0.f);
                float h3 = fmaxf(c[f][3] + b.y, 0.f);
#pragma unroll
                for (int ch = 0; ch < 3; ch++) {
                    float2 w3 = *(const float2*)(sm + F_RW3 + ch * 128 + cb);
                    pA[ch] = fmaf(h0, w3.x, fmaf(h1, w3.y, pA[ch]));
                    pB[ch] = fmaf(h2, w3.x, fmaf(h3, w3.y, pB[ch]));
                }
            }
#pragma unroll
            for (int ch = 0; ch < 3; ch++) {
                pA[ch] += __shfl_xor_sync(0xffffffffu, pA[ch], 1);
                pA[ch] += __shfl_xor_sync(0xffffffffu, pA[ch], 2);
                pB[ch] += __shfl_xor_sync(0xffffffffu, pB[ch], 1);
                pB[ch] += __shfl_xor_sync(0xffffffffu, pB[ch], 2);
            }
            if (qq == 0) {
#pragma unroll
                for (int ch = 0; ch < 3; ch++) {
                    sm[F_RGBP + ch * 128 + nh * 64 + m0 + rr]     = pA[ch];
                    sm[F_RGBP + ch * 128 + nh * 64 + m0 + rr + 8] = pB[ch];
                }
            }
        }
        __syncthreads();

        // ---- combine + store ----
        if (tid < 64) {
            float4 o;
            o.x = sm[F_RGBP + 0 * 128 + tid] + sm[F_RGBP + 0 * 128 + 64 + tid] + sm[F_RB3 + 0];
            o.y = sm[F_RGBP + 1 * 128 + tid] + sm[F_RGBP + 1 * 128 + 64 + tid] + sm[F_RB3 + 1];
            o.z = sm[F_RGBP + 2 * 128 + tid] + sm[F_RGBP + 2 * 128 + 64 + tid] + sm[F_RB3 + 2];
            o.w = sm[F_SDFP + tid] + sm[F_SDFP + 64 + tid] + sm[F_DB3];
            *(float4*)(out + (size_t)(base + tid) * 4) = o;
        }
        __syncthreads();
    }
}

extern "C" void kernel_launch(void* const* d_in, const int* in_sizes, int n_in,
                              void* d_out, int out_size) {
    (void)in_sizes; (void)n_in; (void)out_size;
    const float* x    = (const float*)d_in[0];
    const float* grid = (const float*)d_in[1];
    const float* dW1  = (const float*)d_in[2];
    const float* db1  = (const float*)d_in[3];
    const float* dW2  = (const float*)d_in[4];
    const float* db2  = (const float*)d_in[5];
    const float* dW3  = (const float*)d_in[6];
    const float* db3  = (const float*)d_in[7];
    const float* rW1  = (const float*)d_in[8];
    const float* rb1  = (const float*)d_in[9];
    const float* rW2  = (const float*)d_in[10];
    const float* rb2  = (const float*)d_in[11];
    const float* rW3  = (const float*)d_in[12];
    const float* rb3  = (const float*)d_in[13];
    float* out = (float*)d_out;

    int nsm = 148;
    cudaDeviceGetAttribute(&nsm, cudaDevAttrMultiProcessorCount, 0);
    cudaFuncSetAttribute(fastsurf_mma,
                         cudaFuncAttributeMaxDynamicSharedMemorySize, SMEM_BYTES);
    fastsurf_mma<<<nsm, 256, SMEM_BYTES>>>(x, grid, dW1, db1, dW2, db2, dW3, db3,
                                           rW1, rb1, rW2, rb2, rW3, rb3, out);
}

// round 10
// speedup vs baseline: 3.9722x; 1.0991x over previous
#include <cuda_runtime.h>
#include <math.h>
#include <stdint.h>

#define NPTS   (1 << 20)
#define RESG   160
#define TILE   64
#define NTILES (NPTS / TILE)

#define AS_RF 52    // rf stride (52 mod 32 = 20 -> conflict-free for (r*52+q+k))
#define ST    132   // h / W2t stride (132 mod 32 = 4 -> conflict-free)

// ---- smem float offsets ----
#define F_DW2T 0                       // 128*132
#define F_RW2T (F_DW2T + 16896)
#define F_HD   (F_RW2T + 16896)        // 64*132
#define F_HR   (F_HD + 8448)
#define F_RF   (F_HR + 8448)           // 64*52
#define F_DB1  (F_RF + 3328)
#define F_DB2  (F_DB1 + 128)
#define F_RB1  (F_DB2 + 128)
#define F_RB2  (F_RB1 + 128)
#define F_DW3  (F_RB2 + 128)
#define F_RW3  (F_DW3 + 128)           // [3][128]
#define F_DB3  (F_RW3 + 384)
#define F_RB3  (F_DB3 + 1)             // 3
#define F_PD   (F_RB3 + 3)             // [2][64]
#define F_PR   (F_PD + 128)            // [3][2][64]
#define SMEM_FLOATS (F_PR + 384)
#define SMEM_BYTES  (SMEM_FLOATS * 4)

#define BARC(id)  asm volatile("bar.sync %0, 128;" :: "r"(id) : "memory")
#define BARALL()  asm volatile("bar.sync 0, 256;" ::: "memory")

__device__ __forceinline__ float rtf32(float f) {
    uint32_t u;
    asm("cvt.rna.tf32.f32 %0, %1;" : "=r"(u) : "f"(f));
    return __uint_as_float(u);
}

__device__ __forceinline__ void mma8(float c[4], const uint32_t a[4],
                                     uint32_t b0, uint32_t b1) {
    asm volatile(
        "mma.sync.aligned.m16n8k8.row.col.f32.tf32.tf32.f32 "
        "{%0,%1,%2,%3}, {%4,%5,%6,%7}, {%8,%9}, {%0,%1,%2,%3};"
        : "+f"(c[0]), "+f"(c[1]), "+f"(c[2]), "+f"(c[3])
        : "r"(a[0]), "r"(a[1]), "r"(a[2]), "r"(a[3]), "r"(b0), "r"(b1));
}

// featurize 32 points with 128 threads (4 threads/pt, 2 corners each)
__device__ __forceinline__ void featurize(float* __restrict__ sm,
                                          const float* __restrict__ x,
                                          const float* __restrict__ grid,
                                          int base, int tid128, int pofs) {
    const int p = (tid128 >> 2) + pofs, s2 = tid128 & 3;
    const float* xp = x + (size_t)(base + p) * 8;
    float px = fminf(fmaxf(xp[0], 0.f), 1.f);
    float py = fminf(fmaxf(xp[1], 0.f), 1.f);
    float pz = fminf(fmaxf(xp[2], 0.f), 1.f);
    float fx = px * 159.f, fy = py * 159.f, fz = pz * 159.f;
    float x0f = fminf(floorf(fx), 158.f);
    float y0f = fminf(floorf(fy), 158.f);
    float z0f = fminf(floorf(fz), 158.f);
    float wx = fx - x0f, wy = fy - y0f, wz = fz - z0f;
    int hy = s2 >> 1, hz = s2 & 1;
    int yi = (int)y0f + hy, zi = (int)z0f + hz;
    float wyz = (hy ? wy : 1.f - wy) * (hz ? wz : 1.f - wz);
    float gv[12];
#pragma unroll
    for (int cc = 0; cc < 12; cc++) gv[cc] = 0.f;
#pragma unroll
    for (int hx = 0; hx < 2; hx++) {
        int xi = (int)x0f + hx;
        float w = (hx ? wx : 1.f - wx) * wyz;
        const float* gp = grid + (size_t)((xi * RESG + yi) * RESG + zi) * 12;
        float4 g0 = *(const float4*)gp;
        float4 g1 = *(const float4*)(gp + 4);
        float4 g2 = *(const float4*)(gp + 8);
        gv[0] = fmaf(w, g0.x, gv[0]);  gv[1] = fmaf(w, g0.y, gv[1]);
        gv[2] = fmaf(w, g0.z, gv[2]);  gv[3] = fmaf(w, g0.w, gv[3]);
        gv[4] = fmaf(w, g1.x, gv[4]);  gv[5] = fmaf(w, g1.y, gv[5]);
        gv[6] = fmaf(w, g1.z, gv[6]);  gv[7] = fmaf(w, g1.w, gv[7]);
        gv[8] = fmaf(w, g2.x, gv[8]);  gv[9] = fmaf(w, g2.y, gv[9]);
        gv[10] = fmaf(w, g2.z, gv[10]); gv[11] = fmaf(w, g2.w, gv[11]);
    }
#pragma unroll
    for (int cc = 0; cc < 12; cc++) {
        gv[cc] += __shfl_xor_sync(0xffffffffu, gv[cc], 1);
        gv[cc] += __shfl_xor_sync(0xffffffffu, gv[cc], 2);
    }
    float* rp = sm + F_RF + p * AS_RF;
    if (s2 == 0) {
#pragma unroll
        for (int cc = 0; cc < 12; cc++) rp[cc] = rtf32(gv[cc]);
        rp[39] = rtf32(xp[3]);
        rp[40] = rtf32(xp[4]);
    } else {
        int d = s2 - 1;
        float vv = xp[5 + d];
        rp[12 + d] = rtf32(vv);
        float f = 1.f;
#pragma unroll
        for (int k = 0; k < 4; k++) {
            rp[15 + 6 * k + d]     = rtf32(sinf(vv * f));
            rp[15 + 6 * k + 3 + d] = rtf32(cosf(vv * f));
            f *= 2.f;
        }
    }
}

__global__ void __launch_bounds__(256, 1) fastsurf_ws(
    const float* __restrict__ x, const float* __restrict__ grid,
    const float* __restrict__ dW1, const float* __restrict__ db1,
    const float* __restrict__ dW2, const float* __restrict__ db2,
    const float* __restrict__ dW3, const float* __restrict__ db3,
    const float* __restrict__ rW1, const float* __restrict__ rb1,
    const float* __restrict__ rW2, const float* __restrict__ rb2,
    const float* __restrict__ rW3, const float* __restrict__ rb3,
    float* __restrict__ out) {
    extern __shared__ float sm[];
    const int tid = threadIdx.x;

    // ---- one-time staging ----
    for (int i = tid; i < 128 * ST; i += 256) {
        int n = i / ST, k = i % ST;
        sm[F_DW2T + i] = (k < 128) ? rtf32(dW2[k * 128 + n]) : 0.f;
        sm[F_RW2T + i] = (k < 128) ? rtf32(rW2[k * 128 + n]) : 0.f;
    }
    if (tid < 128) {
        sm[F_DB1 + tid] = db1[tid];
        sm[F_DB2 + tid] = db2[tid];
        sm[F_RB1 + tid] = rb1[tid];
        sm[F_RB2 + tid] = rb2[tid];
        sm[F_DW3 + tid] = dW3[tid];
        sm[F_RW3 + 0 * 128 + tid] = rW3[tid * 3 + 0];
        sm[F_RW3 + 1 * 128 + tid] = rW3[tid * 3 + 1];
        sm[F_RW3 + 2 * 128 + tid] = rW3[tid * 3 + 2];
    }
    if (tid == 0) sm[F_DB3] = db3[0];
    if (tid < 3) sm[F_RB3 + tid] = rb3[tid];
    // zero rf pad cols 41..47 (read by rgb L1 K=48 against zero weights)
    for (int i = tid; i < 64 * 7; i += 256) {
        int row = i / 7, c = 41 + i % 7;
        sm[F_RF + row * AS_RF + c] = 0.f;
    }
    __syncthreads();

    const int lane = tid & 31, warp = tid >> 5;
    const int r = lane >> 2, q = lane & 3;
    const int cw = warp & 3;
    const int mi = cw & 1, ni = cw >> 1;
    const int m0 = mi * 32, n0 = ni * 64;
    const int tid128 = tid & 127;

    if (warp < 4) {
        // ================= DENSITY CHAIN (warps 0-3) =================
        uint32_t dB[2][8][2];
#pragma unroll
        for (int ks = 0; ks < 2; ks++)
#pragma unroll
            for (int f = 0; f < 8; f++)
#pragma unroll
                for (int j2 = 0; j2 < 2; j2++) {
                    int k = 8 * ks + q + 4 * j2;
                    int n = n0 + f * 8 + r;
                    dB[ks][f][j2] = (k < 12) ? __float_as_uint(rtf32(dW1[k * 128 + n])) : 0u;
                }

        for (int tile = blockIdx.x; tile < NTILES; tile += gridDim.x) {
            const int base = tile * TILE;
            featurize(sm, x, grid, base, tid128, 0);
            BARALL();

            float c[2][8][4];
#pragma unroll
            for (int mb = 0; mb < 2; mb++)
#pragma unroll
                for (int f = 0; f < 8; f++)
                    c[mb][f][0] = c[mb][f][1] = c[mb][f][2] = c[mb][f][3] = 0.f;

            // L1: rf(K16) x dW1 (B in regs)
            const float* ap = sm + F_RF + (m0 + r) * AS_RF + q;
#pragma unroll
            for (int ks = 0; ks < 2; ks++) {
                const int k = 8 * ks;
                uint32_t a[2][4];
#pragma unroll
                for (int mb = 0; mb < 2; mb++) {
                    const float* am = ap + mb * 16 * AS_RF;
                    a[mb][0] = __float_as_uint(am[k]);
                    a[mb][1] = __float_as_uint(am[8 * AS_RF + k]);
                    a[mb][2] = __float_as_uint(am[k + 4]);
                    a[mb][3] = __float_as_uint(am[8 * AS_RF + k + 4]);
                }
#pragma unroll
                for (int f = 0; f < 8; f++)
#pragma unroll
                    for (int mb = 0; mb < 2; mb++)
                        mma8(c[mb][f], a[mb], dB[ks][f][0], dB[ks][f][1]);
            }
            // epilogue -> h_d
#pragma unroll
            for (int f = 0; f < 8; f++) {
                int cb = n0 + f * 8 + 2 * q;
                float2 b = *(const float2*)(sm + F_DB1 + cb);
#pragma unroll
                for (int mb = 0; mb < 2; mb++) {
                    float* hp = sm + F_HD + (m0 + mb * 16 + r) * ST + cb;
                    *(float2*)hp = make_float2(rtf32(fmaxf(c[mb][f][0] + b.x, 0.f)),
                                               rtf32(fmaxf(c[mb][f][1] + b.y, 0.f)));
                    *(float2*)(hp + 8 * ST) = make_float2(rtf32(fmaxf(c[mb][f][2] + b.x, 0.f)),
                                                          rtf32(fmaxf(c[mb][f][3] + b.y, 0.f)));
                }
            }
            BARC(1);

            // L2: h_d(K128) x dW2
#pragma unroll
            for (int mb = 0; mb < 2; mb++)
#pragma unroll
                for (int f = 0; f < 8; f++)
                    c[mb][f][0] = c[mb][f][1] = c[mb][f][2] = c[mb][f][3] = 0.f;
            const float* hp0 = sm + F_HD + (m0 + r) * ST + q;
            const float* wp0 = sm + F_DW2T + (n0 + r) * ST + q;
#pragma unroll
            for (int ks = 0; ks < 16; ks++) {
                const int k = 8 * ks;
                uint32_t b[8][2];
#pragma unroll
                for (int f = 0; f < 8; f++) {
                    b[f][0] = __float_as_uint(wp0[f * 8 * ST + k]);
                    b[f][1] = __float_as_uint(wp0[f * 8 * ST + k + 4]);
                }
                uint32_t a[2][4];
#pragma unroll
                for (int mb = 0; mb < 2; mb++) {
                    const float* am = hp0 + mb * 16 * ST;
                    a[mb][0] = __float_as_uint(am[k]);
                    a[mb][1] = __float_as_uint(am[8 * ST + k]);
                    a[mb][2] = __float_as_uint(am[k + 4]);
                    a[mb][3] = __float_as_uint(am[8 * ST + k + 4]);
                }
#pragma unroll
                for (int f = 0; f < 8; f++)
#pragma unroll
                    for (int mb = 0; mb < 2; mb++)
                        mma8(c[mb][f], a[mb], b[f][0], b[f][1]);
            }
            // fused sdf head
            float ps[2][2] = {{0.f, 0.f}, {0.f, 0.f}};
#pragma unroll
            for (int f = 0; f < 8; f++) {
                int cb = n0 + f * 8 + 2 * q;
                float2 b2 = *(const float2*)(sm + F_DB2 + cb);
                float2 w3 = *(const float2*)(sm + F_DW3 + cb);
#pragma unroll
                for (int mb = 0; mb < 2; mb++) {
                    ps[mb][0] = fmaf(fmaxf(c[mb][f][0] + b2.x, 0.f), w3.x,
                                fmaf(fmaxf(c[mb][f][1] + b2.y, 0.f), w3.y, ps[mb][0]));
                    ps[mb][1] = fmaf(fmaxf(c[mb][f][2] + b2.x, 0.f), w3.x,
                                fmaf(fmaxf(c[mb][f][3] + b2.y, 0.f), w3.y, ps[mb][1]));
                }
            }
#pragma unroll
            for (int mb = 0; mb < 2; mb++)
#pragma unroll
                for (int hh = 0; hh < 2; hh++) {
                    ps[mb][hh] += __shfl_xor_sync(0xffffffffu, ps[mb][hh], 1);
                    ps[mb][hh] += __shfl_xor_sync(0xffffffffu, ps[mb][hh], 2);
                }
            if (q == 0) {
#pragma unroll
                for (int mb = 0; mb < 2; mb++) {
                    sm[F_PD + ni * 64 + m0 + mb * 16 + r]     = ps[mb][0];
                    sm[F_PD + ni * 64 + m0 + mb * 16 + r + 8] = ps[mb][1];
                }
            }
            BARC(1);
            if (tid < 64)
                out[(size_t)(base + tid) * 4 + 3] =
                    sm[F_PD + tid] + sm[F_PD + 64 + tid] + sm[F_DB3];
            BARALL();
        }
    } else {
        // ================= RGB CHAIN (warps 4-7) =================
        uint32_t rB[6][8][2];
#pragma unroll
        for (int ks = 0; ks < 6; ks++)
#pragma unroll
            for (int f = 0; f < 8; f++)
#pragma unroll
                for (int j2 = 0; j2 < 2; j2++) {
                    int k = 8 * ks + q + 4 * j2;
                    int n = n0 + f * 8 + r;
                    rB[ks][f][j2] = (k < 41) ? __float_as_uint(rtf32(rW1[k * 128 + n])) : 0u;
                }

        for (int tile = blockIdx.x; tile < NTILES; tile += gridDim.x) {
            const int base = tile * TILE;
            featurize(sm, x, grid, base, tid128, 32);
            BARALL();

            float c[2][8][4];
#pragma unroll
            for (int mb = 0; mb < 2; mb++)
#pragma unroll
                for (int f = 0; f < 8; f++)
                    c[mb][f][0] = c[mb][f][1] = c[mb][f][2] = c[mb][f][3] = 0.f;

            // L1: rf(K48) x rW1 (B in regs)
            const float* ap = sm + F_RF + (m0 + r) * AS_RF + q;
#pragma unroll
            for (int ks = 0; ks < 6; ks++) {
                const int k = 8 * ks;
                uint32_t a[2][4];
#pragma unroll
                for (int mb = 0; mb < 2; mb++) {
                    const float* am = ap + mb * 16 * AS_RF;
                    a[mb][0] = __float_as_uint(am[k]);
                    a[mb][1] = __float_as_uint(am[8 * AS_RF + k]);
                    a[mb][2] = __float_as_uint(am[k + 4]);
                    a[mb][3] = __float_as_uint(am[8 * AS_RF + k + 4]);
                }
#pragma unroll
                for (int f = 0; f < 8; f++)
#pragma unroll
                    for (int mb = 0; mb < 2; mb++)
                        mma8(c[mb][f], a[mb], rB[ks][f][0], rB[ks][f][1]);
            }
            // epilogue -> h_r
#pragma unroll
            for (int f = 0; f < 8; f++) {
                int cb = n0 + f * 8 + 2 * q;
                float2 b = *(const float2*)(sm + F_RB1 + cb);
#pragma unroll
                for (int mb = 0; mb < 2; mb++) {
                    float* hp = sm + F_HR + (m0 + mb * 16 + r) * ST + cb;
                    *(float2*)hp = make_float2(rtf32(fmaxf(c[mb][f][0] + b.x, 0.f)),
                                               rtf32(fmaxf(c[mb][f][1] + b.y, 0.f)));
                    *(float2*)(hp + 8 * ST) = make_float2(rtf32(fmaxf(c[mb][f][2] + b.x, 0.f)),
                                                          rtf32(fmaxf(c[mb][f][3] + b.y, 0.f)));
                }
            }
            BARC(2);

            // L2: h_r(K128) x rW2
#pragma unroll
            for (int mb = 0; mb < 2; mb++)
#pragma unroll
                for (int f = 0; f < 8; f++)
                    c[mb][f][0] = c[mb][f][1] = c[mb][f][2] = c[mb][f][3] = 0.f;
            const float* hp0 = sm + F_HR + (m0 + r) * ST + q;
            const float* wp0 = sm + F_RW2T + (n0 + r) * ST + q;
#pragma unroll
            for (int ks = 0; ks < 16; ks++) {
                const int k = 8 * ks;
                uint32_t b[8][2];
#pragma unroll
                for (int f = 0; f < 8; f++) {
                    b[f][0] = __float_as_uint(wp0[f * 8 * ST + k]);
                    b[f][1] = __float_as_uint(wp0[f * 8 * ST + k + 4]);
                }
                uint32_t a[2][4];
#pragma unroll
                for (int mb = 0; mb < 2; mb++) {
                    const float* am = hp0 + mb * 16 * ST;
                    a[mb][0] = __float_as_uint(am[k]);
                    a[mb][1] = __float_as_uint(am[8 * ST + k]);
                    a[mb][2] = __float_as_uint(am[k + 4]);
                    a[mb][3] = __float_as_uint(am[8 * ST + k + 4]);
                }
#pragma unroll
                for (int f = 0; f < 8; f++)
#pragma unroll
                    for (int mb = 0; mb < 2; mb++)
                        mma8(c[mb][f], a[mb], b[f][0], b[f][1]);
            }
            // fused rgb head (3 channels)
            float pc[3][2][2];
#pragma unroll
            for (int ch = 0; ch < 3; ch++)
#pragma unroll
                for (int mb = 0; mb < 2; mb++)
                    pc[ch][mb][0] = pc[ch][mb][1] = 0.f;
#pragma unroll
            for (int f = 0; f < 8; f++) {
                int cb = n0 + f * 8 + 2 * q;
                float2 b2 = *(const float2*)(sm + F_RB2 + cb);
#pragma unroll
                for (int mb = 0; mb < 2; mb++) {
                    float h0 = fmaxf(c[mb][f][0] + b2.x, 0.f);
                    float h1 = fmaxf(c[mb][f][1] + b2.y, 0.f);
                    float h2 = fmaxf(c[mb][f][2] + b2.x, 0.f);
                    float h3 = fmaxf(c[mb][f][3] + b2.y, 0.f);
#pragma unroll
                    for (int ch = 0; ch < 3; ch++) {
                        float2 w3 = *(const float2*)(sm + F_RW3 + ch * 128 + cb);
                        pc[ch][mb][0] = fmaf(h0, w3.x, fmaf(h1, w3.y, pc[ch][mb][0]));
                        pc[ch][mb][1] = fmaf(h2, w3.x, fmaf(h3, w3.y, pc[ch][mb][1]));
                    }
                }
            }
#pragma unroll
            for (int ch = 0; ch < 3; ch++)
#pragma unroll
                for (int mb = 0; mb < 2; mb++)
#pragma unroll
                    for (int hh = 0; hh < 2; hh++) {
                        pc[ch][mb][hh] += __shfl_xor_sync(0xffffffffu, pc[ch][mb][hh], 1);
                        pc[ch][mb][hh] += __shfl_xor_sync(0xffffffffu, pc[ch][mb][hh], 2);
                    }
            if (q == 0) {
#pragma unroll
                for (int ch = 0; ch < 3; ch++)
#pragma unroll
                    for (int mb = 0; mb < 2; mb++) {
                        sm[F_PR + ch * 128 + ni * 64 + m0 + mb * 16 + r]     = pc[ch][mb][0];
                        sm[F_PR + ch * 128 + ni * 64 + m0 + mb * 16 + r + 8] = pc[ch][mb][1];
                    }
            }
            BARC(2);
            if (tid128 < 64) {
                int p = tid128;
#pragma unroll
                for (int ch = 0; ch < 3; ch++)
                    out[(size_t)(base + p) * 4 + ch] =
                        sm[F_PR + ch * 128 + p] + sm[F_PR + ch * 128 + 64 + p] + sm[F_RB3 + ch];
            }
            BARALL();
        }
    }
}

extern "C" void kernel_launch(void* const* d_in, const int* in_sizes, int n_in,
                              void* d_out, int out_size) {
    (void)in_sizes; (void)n_in; (void)out_size;
    const float* x    = (const float*)d_in[0];
    const float* grid = (const float*)d_in[1];
    const float* dW1  = (const float*)d_in[2];
    const float* db1  = (const float*)d_in[3];
    const float* dW2  = (const float*)d_in[4];
    const float* db2  = (const float*)d_in[5];
    const float* dW3  = (const float*)d_in[6];
    const float* db3  = (const float*)d_in[7];
    const float* rW1  = (const float*)d_in[8];
    const float* rb1  = (const float*)d_in[9];
    const float* rW2  = (const float*)d_in[10];
    const float* rb2  = (const float*)d_in[11];
    const float* rW3  = (const float*)d_in[12];
    const float* rb3  = (const float*)d_in[13];
    float* out = (float*)d_out;

    int nsm = 148;
    cudaDeviceGetAttribute(&nsm, cudaDevAttrMultiProcessorCount, 0);
    cudaFuncSetAttribute(fastsurf_ws,
                         cudaFuncAttributeMaxDynamicSharedMemorySize, SMEM_BYTES);
    fastsurf_ws<<<nsm, 256, SMEM_BYTES>>>(x, grid, dW1, db1, dW2, db2, dW3, db3,
                                          rW1, rb1, rW2, rb2, rW3, rb3, out);
}